// round 10
// baseline (speedup 1.0000x reference)
#include <cuda_runtime.h>
#include <math.h>

// Problem constants
#define B_   32
#define N_   4096
#define D_   256
#define S_   16
#define K_   8
#define H_   128
#define LN_EPS 1e-5f
#define EPS_ 1e-8f
#define SCALE_ 0.25f

#define ML_GRID 512          // 32 batches x 16 groups of 256 n
#define ML_NT 256            // n per block
#define ML_THREADS 256
#define KV_PITCH 36

// ---------------- device scratch ----------------
__device__ __align__(16) float g_wt[D_ * 32];   // wt[d][c], c<16: wk*lnw, c>=16: wv*lnw
__device__ float g_c1[32];
__device__ float g_c2[32];
__device__ __align__(16) float g_kv[(long long)B_ * N_ * 32];  // [b][n][k0..15|v0..15]
__device__ float g_num3[3 * B_ * K_ * S_];      // per-iteration accumulators
__device__ float g_den3[3 * B_ * K_];
__device__ unsigned g_bar;

// ---------------- f32x2 helpers ----------------
__device__ __forceinline__ unsigned long long pack2(float lo, float hi) {
    unsigned long long r;
    asm("mov.b64 %0, {%1, %2};" : "=l"(r) : "f"(lo), "f"(hi));
    return r;
}
__device__ __forceinline__ void unpack2(unsigned long long v, float& lo, float& hi) {
    asm("mov.b64 {%0, %1}, %2;" : "=f"(lo), "=f"(hi) : "l"(v));
}
__device__ __forceinline__ void fma2(unsigned long long& d, unsigned long long a, unsigned long long b) {
    asm("fma.rn.f32x2 %0, %1, %2, %0;" : "+l"(d) : "l"(a), "l"(b));
}

// ---------------- prep (R8-pass verbatim) ----------------
__global__ void __launch_bounds__(1024) prep_kernel(
    const float* __restrict__ wk, const float* __restrict__ wv,
    const float* __restrict__ ln_w, const float* __restrict__ ln_b) {
    const int t = threadIdx.x;  // 1024
#pragma unroll
    for (int i = 0; i < 8; i++) {
        int idx = t + i * 1024;
        int c = idx & 31, d = idx >> 5;
        float w = (c < 16) ? wk[c * D_ + d] : wv[(c - 16) * D_ + d];
        g_wt[d * 32 + c] = w * ln_w[d];
    }
    {
        int w = t >> 5, l = t & 31;
        const float* wr = (w < 16) ? &wk[w * D_] : &wv[(w - 16) * D_];
        float c1 = 0.f, c2 = 0.f;
#pragma unroll
        for (int j = 0; j < 8; j++) {
            int d = l + j * 32;
            float wv_ = wr[d];
            c1 = fmaf(wv_, ln_w[d], c1);
            c2 = fmaf(wv_, ln_b[d], c2);
        }
#pragma unroll
        for (int o = 16; o >= 1; o >>= 1) {
            c1 += __shfl_xor_sync(0xffffffffu, c1, o);
            c2 += __shfl_xor_sync(0xffffffffu, c2, o);
        }
        if (l == 0) {
            g_c1[w] = c1;
            g_c2[w] = c2;
        }
    }
#pragma unroll
    for (int i = 0; i < 12; i++) g_num3[t + i * 1024] = 0.f;
    if (t < 768) g_den3[t] = 0.f;
    if (t == 0) g_bar = 0u;
}

// ---------------- fused LayerNorm + k/v projection (R8-pass verbatim) ----------------
#define LP_ROWS 64
#define LP_THREADS 128
#define LP_XS_PITCH 257
#define LP_SMEM_FLOATS (LP_ROWS * LP_XS_PITCH + D_ * 32 + 2 * LP_ROWS)

__global__ void __launch_bounds__(LP_THREADS) lnproj_kernel(const float* __restrict__ in) {
    extern __shared__ float sm[];
    float* xs = sm;
    float* wt = sm + LP_ROWS * LP_XS_PITCH;
    float* mu_s = wt + D_ * 32;
    float* rs_s = mu_s + LP_ROWS;

    const int t = threadIdx.x;
    const long long row0 = (long long)blockIdx.x * LP_ROWS;

    {
        const float4* src = (const float4*)g_wt;
        float4* dst = (float4*)wt;
#pragma unroll
        for (int i = 0; i < 16; i++) dst[t + i * LP_THREADS] = src[t + i * LP_THREADS];
    }
    {
        const float* src = in + row0 * D_;
#pragma unroll 8
        for (int i = 0; i < 128; i++) {
            int idx = t + i * LP_THREADS;
            int r = idx >> 8, c = idx & 255;
            xs[r * LP_XS_PITCH + c] = src[idx];
        }
    }
    __syncthreads();

    {
        int r = t >> 1, half = t & 1;
        const float* xr = &xs[r * LP_XS_PITCH + half * 128];
        float s = 0.f, ss = 0.f;
#pragma unroll 8
        for (int j = 0; j < 128; j++) {
            float x = xr[j];
            s += x;
            ss = fmaf(x, x, ss);
        }
        s += __shfl_xor_sync(0xffffffffu, s, 1);
        ss += __shfl_xor_sync(0xffffffffu, ss, 1);
        if (half == 0) {
            float mu = s * (1.f / 256.f);
            float var = ss * (1.f / 256.f) - mu * mu;
            mu_s[r] = mu;
            rs_s[r] = rsqrtf(var + LN_EPS);
        }
    }
    __syncthreads();

    const int rr = t & 31;
    const int c0 = (t >> 5) * 8;
    unsigned long long acc[2][4];
#pragma unroll
    for (int p = 0; p < 2; p++)
#pragma unroll
        for (int c = 0; c < 4; c++) acc[p][c] = 0ull;

    const float* xa_p = &xs[rr * LP_XS_PITCH];
    const float* xb_p = &xs[(rr + 32) * LP_XS_PITCH];
#pragma unroll 8
    for (int d = 0; d < D_; d++) {
        float xa = xa_p[d];
        float xb = xb_p[d];
        unsigned long long xa2 = pack2(xa, xa);
        unsigned long long xb2 = pack2(xb, xb);
        ulonglong2 w01 = *(const ulonglong2*)&wt[d * 32 + c0];
        ulonglong2 w23 = *(const ulonglong2*)&wt[d * 32 + c0 + 4];
        fma2(acc[0][0], xa2, w01.x);
        fma2(acc[0][1], xa2, w01.y);
        fma2(acc[0][2], xa2, w23.x);
        fma2(acc[0][3], xa2, w23.y);
        fma2(acc[1][0], xb2, w01.x);
        fma2(acc[1][1], xb2, w01.y);
        fma2(acc[1][2], xb2, w23.x);
        fma2(acc[1][3], xb2, w23.y);
    }

    float c1v[8], c2v[8];
#pragma unroll
    for (int j = 0; j < 8; j++) {
        c1v[j] = g_c1[c0 + j];
        c2v[j] = g_c2[c0 + j];
    }
#pragma unroll
    for (int p = 0; p < 2; p++) {
        int r = rr + 32 * p;
        float mu = mu_s[r], rs = rs_s[r];
        float o[8];
#pragma unroll
        for (int c = 0; c < 4; c++) {
            float lo, hi;
            unpack2(acc[p][c], lo, hi);
            o[2 * c] = fmaf(rs, lo - mu * c1v[2 * c], c2v[2 * c]);
            o[2 * c + 1] = fmaf(rs, hi - mu * c1v[2 * c + 1], c2v[2 * c + 1]);
        }
        float4* dst = (float4*)&g_kv[(row0 + r) * 32 + c0];
        dst[0] = make_float4(o[0], o[1], o[2], o[3]);
        dst[1] = make_float4(o[4], o[5], o[6], o[7]);
    }
}

// ---------------- persistent mainloop (256 threads) ----------------
// smem layout (floats):
//   kvs  [0      : 9216)   256 x 36 kv tile (persistent)
//   slb  [9216   : 9344)   slots for this batch (persistent)
//   qlo  [9344   : 9472)   q for this batch (persistent); reused as inv-den on final
//   S1   [9472   : 11648)  2176: warp-red [8][8][17] / upd|h|y|gi|gh|hid scratch
//   S2   [11648  : 13728)  2080: a_s [8][260] (final iter) / weight staging
#define ML_SMEM_FLOATS 13728

__device__ __forceinline__ void grid_barrier(unsigned target) {
    __syncthreads();
    if (threadIdx.x == 0) {
        __threadfence();
        atomicAdd(&g_bar, 1u);
        while (*((volatile unsigned*)&g_bar) < target) {
            __nanosleep(64);
        }
        __threadfence();
    }
    __syncthreads();
}

__global__ void __launch_bounds__(ML_THREADS, 4) mainloop_kernel(
    const float* __restrict__ init_slots,
    const float* __restrict__ ln_s_w, const float* __restrict__ ln_s_b,
    const float* __restrict__ wq,
    const float* __restrict__ w_ih, const float* __restrict__ w_hh,
    const float* __restrict__ b_ih, const float* __restrict__ b_hh,
    const float* __restrict__ ln_m_w, const float* __restrict__ ln_m_b,
    const float* __restrict__ w1, const float* __restrict__ b1,
    const float* __restrict__ w2, const float* __restrict__ b2,
    float* __restrict__ out_slots, float* __restrict__ out_attn) {
    extern __shared__ float sm[];
    float* kvs = sm;
    float* slb = sm + 9216;
    float* qlo = sm + 9344;
    float* S1 = sm + 9472;
    float* S2 = sm + 11648;

    const int bx = blockIdx.x;
    const int b = bx >> 4;
    const int grp = bx & 15;
    const int n0 = grp * ML_NT;
    const int t = threadIdx.x;          // 0..255
    const int k = t & 7;
    const int g = t >> 3;               // 0..31
    const int lane = t & 31;
    const int warp = t >> 5;            // 0..7

    // stage kv tile once: 256 rows x 32 floats = 2048 float4
    {
        const float4* src = (const float4*)(g_kv + ((long long)b * N_ + n0) * 32);
#pragma unroll
        for (int i = 0; i < 8; i++) {
            int idx = t + i * ML_THREADS;
            int r = idx >> 3, f = idx & 7;
            *(float4*)&kvs[r * KV_PITCH + 4 * f] = src[idx];
        }
    }
    if (t < 128) slb[t] = init_slots[b * 128 + t];
    __syncthreads();

    // initial q (proven qprep body, one thread per slot row)
    if (t < K_) {
        float x[S_];
        float s = 0.f;
#pragma unroll
        for (int j = 0; j < S_; j++) {
            x[j] = slb[t * S_ + j];
            s += x[j];
        }
        float mu = s * (1.f / 16.f);
        float ss = 0.f;
#pragma unroll
        for (int j = 0; j < S_; j++) {
            float d = x[j] - mu;
            ss = fmaf(d, d, ss);
        }
        float rs = rsqrtf(ss * (1.f / 16.f) + LN_EPS);
        float y[S_];
#pragma unroll
        for (int j = 0; j < S_; j++) y[j] = (x[j] - mu) * rs * __ldg(ln_s_w + j) + __ldg(ln_s_b + j);
#pragma unroll
        for (int tt = 0; tt < S_; tt++) {
            float q = 0.f;
#pragma unroll
            for (int j = 0; j < S_; j++) q = fmaf(y[j], __ldg(wq + tt * S_ + j), q);
            qlo[t * S_ + tt] = q;
        }
    }
    __syncthreads();

    for (int it = 0; it < 3; it++) {
        // ---------- attn phase (proven inner body; 32 g-groups x 8 j-steps) ----------
        float qr[S_];
#pragma unroll
        for (int s = 0; s < S_; s++) qr[s] = qlo[k * S_ + s];
        float num[S_];
#pragma unroll
        for (int s = 0; s < S_; s++) num[s] = 0.f;
        float den = 0.f;

#pragma unroll 2
        for (int j = 0; j < ML_NT / 32; j++) {
            int nl = g + 32 * j;
            const float* kn = &kvs[nl * KV_PITCH];
            float logit = 0.f;
#pragma unroll
            for (int s = 0; s < S_; s++) logit = fmaf(qr[s], kn[s], logit);
            logit *= SCALE_;
            float m = logit;
            m = fmaxf(m, __shfl_xor_sync(0xffffffffu, m, 1));
            m = fmaxf(m, __shfl_xor_sync(0xffffffffu, m, 2));
            m = fmaxf(m, __shfl_xor_sync(0xffffffffu, m, 4));
            float e = __expf(logit - m);
            float sum = e;
            sum += __shfl_xor_sync(0xffffffffu, sum, 1);
            sum += __shfl_xor_sync(0xffffffffu, sum, 2);
            sum += __shfl_xor_sync(0xffffffffu, sum, 4);
            float a = e / sum + EPS_;
            if (it == 2) S2[k * (ML_NT + 4) + nl] = a;
            den += a;
            const float* vn = kn + 16;
#pragma unroll
            for (int s = 0; s < S_; s++) num[s] = fmaf(a, vn[s], num[s]);
        }

        // intra-warp pre-reduce over the 4 g-values sharing each k (xor 8, 16)
#pragma unroll
        for (int o = 8; o <= 16; o <<= 1) {
#pragma unroll
            for (int s = 0; s < S_; s++) num[s] += __shfl_xor_sync(0xffffffffu, num[s], o);
            den += __shfl_xor_sync(0xffffffffu, den, o);
        }
        __syncthreads();   // protect S1 reuse across loop iterations
        if (lane < 8) {
            float* rp = &S1[(warp * 8 + lane) * 17];
#pragma unroll
            for (int s = 0; s < S_; s++) rp[s] = num[s];
            rp[16] = den;
        }
        __syncthreads();
        if (t < 136) {  // 8 k * 17 vals
            int k2 = t / 17, s2 = t % 17;
            float v = 0.f;
#pragma unroll
            for (int w = 0; w < 8; w++) v += S1[(w * 8 + k2) * 17 + s2];
            if (s2 < 16)
                atomicAdd(&g_num3[it * 4096 + b * 128 + k2 * 16 + s2], v);
            else
                atomicAdd(&g_den3[it * 256 + b * K_ + k2], v);
        }

        // ---------- grid barrier ----------
        grid_barrier((unsigned)ML_GRID * (unsigned)(it + 1));

        // ---------- read reduced num/den ----------
        if (t < 128) {
            float u_num = __ldcg(&g_num3[it * 4096 + b * 128 + t]);
            float u_den = __ldcg(&g_den3[it * 256 + b * K_ + (t >> 4)]);
            S1[t] = u_num / u_den;  // upd
        }

        if (it == 2) {
            if (t < K_) qlo[t] = 1.0f / __ldcg(&g_den3[it * 256 + b * K_ + t]);
            __syncthreads();
#pragma unroll 4
            for (int i = t; i < K_ * ML_NT; i += ML_THREADS) {
                int kk = i >> 8, nn = i & (ML_NT - 1);
                out_attn[((long long)(b * K_ + kk)) * N_ + n0 + nn] =
                    S2[kk * (ML_NT + 4) + nn] * qlo[kk];
            }
        }
        __syncthreads();

        // ---------- update phase (proven math; generic 256-thread strides) ----------
        for (int i = t; i < 768; i += ML_THREADS) {
            S2[i] = __ldg(w_ih + i);
            S2[768 + i] = __ldg(w_hh + i);
        }
        __syncthreads();
        for (int idx = t; idx < 384; idx += ML_THREADS) {
            int kk = idx / 48, j = idx % 48;
            float gi = __ldg(b_ih + j), gh = __ldg(b_hh + j);
#pragma unroll
            for (int s = 0; s < S_; s++) {
                gi = fmaf(S1[kk * S_ + s], S2[j * S_ + s], gi);
                gh = fmaf(slb[kk * S_ + s], S2[768 + j * S_ + s], gh);
            }
            S1[384 + idx] = gi;
            S1[768 + idx] = gh;
        }
        __syncthreads();
        if (t < 128) {
            int kk = t >> 4, s = t & 15;
            float ir = S1[384 + kk * 48 + s], hr = S1[768 + kk * 48 + s];
            float iz = S1[384 + kk * 48 + 16 + s], hz = S1[768 + kk * 48 + 16 + s];
            float inn = S1[384 + kk * 48 + 32 + s], hn = S1[768 + kk * 48 + 32 + s];
            float r = 1.f / (1.f + __expf(-(ir + hr)));
            float z = 1.f / (1.f + __expf(-(iz + hz)));
            float n = tanhf(inn + r * hn);
            float h = (1.f - z) * n + z * slb[t];
            S1[128 + t] = h;  // h_s
            float s1 = h, s2 = h * h;
#pragma unroll
            for (int o = 1; o <= 8; o <<= 1) {
                s1 += __shfl_xor_sync(0xffffffffu, s1, o);
                s2 += __shfl_xor_sync(0xffffffffu, s2, o);
            }
            float mu = s1 * (1.f / 16.f);
            float var = s2 * (1.f / 16.f) - mu * mu;
            float rs = rsqrtf(var + LN_EPS);
            S1[256 + t] = (h - mu) * rs * __ldg(ln_m_w + s) + __ldg(ln_m_b + s);  // y_s
        }
        __syncthreads();
        for (int i = t; i < H_ * S_; i += ML_THREADS) S2[i] = __ldg(w1 + i);
        __syncthreads();
        for (int idx = t; idx < K_ * H_; idx += ML_THREADS) {
            int kk = idx >> 7, hh = idx & 127;
            float acc = __ldg(b1 + hh);
#pragma unroll
            for (int s = 0; s < S_; s++) acc = fmaf(S1[256 + kk * S_ + s], S2[hh * S_ + s], acc);
            S1[1152 + idx] = fmaxf(acc, 0.f);  // hid
        }
        __syncthreads();
        for (int i = t; i < S_ * H_; i += ML_THREADS) S2[i] = __ldg(w2 + i);
        __syncthreads();
        float res = 0.f;
        if (t < 128) {
            int kk = t >> 4, s = t & 15;
            float acc = __ldg(b2 + s);
#pragma unroll 8
            for (int h = 0; h < H_; h++) acc = fmaf(S1[1152 + kk * H_ + h], S2[s * H_ + h], acc);
            res = S1[128 + t] + acc;
        }

        if (it == 2) {
            if (grp == 0 && t < 128) out_slots[b * 128 + t] = res;
        } else {
            __syncthreads();
            if (t < 128) slb[t] = res;
            __syncthreads();
            if (t < K_) {
                float x[S_];
                float s = 0.f;
#pragma unroll
                for (int j = 0; j < S_; j++) {
                    x[j] = slb[t * S_ + j];
                    s += x[j];
                }
                float mu = s * (1.f / 16.f);
                float ss = 0.f;
#pragma unroll
                for (int j = 0; j < S_; j++) {
                    float d = x[j] - mu;
                    ss = fmaf(d, d, ss);
                }
                float rs = rsqrtf(ss * (1.f / 16.f) + LN_EPS);
                float y[S_];
#pragma unroll
                for (int j = 0; j < S_; j++)
                    y[j] = (x[j] - mu) * rs * __ldg(ln_s_w + j) + __ldg(ln_s_b + j);
#pragma unroll
                for (int tt = 0; tt < S_; tt++) {
                    float q = 0.f;
#pragma unroll
                    for (int j = 0; j < S_; j++) q = fmaf(y[j], __ldg(wq + tt * S_ + j), q);
                    qlo[t * S_ + tt] = q;
                }
            }
            __syncthreads();
        }
    }
}

// ---------------- launch: 3 graph nodes ----------------
extern "C" void kernel_launch(void* const* d_in, const int* in_sizes, int n_in,
                              void* d_out, int out_size) {
    const float* inputs = (const float*)d_in[0];
    const float* init_slots = (const float*)d_in[1];
    const float* ln_in_w = (const float*)d_in[2];
    const float* ln_in_b = (const float*)d_in[3];
    const float* ln_s_w = (const float*)d_in[4];
    const float* ln_s_b = (const float*)d_in[5];
    const float* ln_m_w = (const float*)d_in[6];
    const float* ln_m_b = (const float*)d_in[7];
    const float* wq = (const float*)d_in[8];
    const float* wk = (const float*)d_in[9];
    const float* wv = (const float*)d_in[10];
    const float* w_ih = (const float*)d_in[11];
    const float* w_hh = (const float*)d_in[12];
    const float* b_ih = (const float*)d_in[13];
    const float* b_hh = (const float*)d_in[14];
    const float* mlp_w1 = (const float*)d_in[15];
    const float* mlp_b1 = (const float*)d_in[16];
    const float* mlp_w2 = (const float*)d_in[17];
    const float* mlp_b2 = (const float*)d_in[18];

    float* out_slots = (float*)d_out;
    float* out_attn = out_slots + B_ * K_ * S_;

    const int lp_smem = LP_SMEM_FLOATS * sizeof(float);
    cudaFuncSetAttribute(lnproj_kernel, cudaFuncAttributeMaxDynamicSharedMemorySize, lp_smem);
    const int ml_smem = ML_SMEM_FLOATS * sizeof(float);
    cudaFuncSetAttribute(mainloop_kernel, cudaFuncAttributeMaxDynamicSharedMemorySize, ml_smem);

    prep_kernel<<<1, 1024>>>(wk, wv, ln_in_w, ln_in_b);
    lnproj_kernel<<<(B_ * N_) / LP_ROWS, LP_THREADS, lp_smem>>>(inputs);
    mainloop_kernel<<<ML_GRID, ML_THREADS, ml_smem>>>(
        init_slots, ln_s_w, ln_s_b, wq, w_ih, w_hh, b_ih, b_hh,
        ln_m_w, ln_m_b, mlp_w1, mlp_b1, mlp_w2, mlp_b2, out_slots, out_attn);
}

// round 12
// speedup vs baseline: 1.2193x; 1.2193x over previous
#include <cuda_runtime.h>
#include <cuda_bf16.h>
#include <math.h>
#include <stdint.h>

// Problem constants
#define B_   32
#define N_   4096
#define D_   256
#define S_   16
#define K_   8
#define H_   128
#define LN_EPS 1e-5f
#define EPS_ 1e-8f
#define SCALE_ 0.25f

#define ML_GRID 512          // 32 batches x 16 groups of 256 n
#define ML_NT 256            // n per block
#define ML_THREADS 256
#define KV_PITCH 36

// ---------------- device scratch ----------------
__device__ float g_c1[32];
__device__ float g_c2[32];
__device__ __align__(16) float g_kv[(long long)B_ * N_ * 32];  // [b][n][k0..15|v0..15]
__device__ __align__(16) unsigned short g_wbh[32 * 256];       // bf16 hi w  [n][k] row-major
__device__ __align__(16) unsigned short g_wbl[32 * 256];       // bf16 lo w
__device__ float g_num3[3 * B_ * K_ * S_];      // per-iteration accumulators
__device__ float g_den3[3 * B_ * K_];
__device__ unsigned g_bar;

__device__ __forceinline__ uint32_t smem_to_u32(const void* smem_ptr) {
    uint32_t addr;
    asm("{ .reg .u64 tmp; cvta.to.shared.u64 tmp, %1; cvt.u32.u64 %0, tmp; }"
        : "=r"(addr) : "l"(smem_ptr));
    return addr;
}

// ---------------- prep: c1/c2 + bf16 w (plain layout) + zero acc + bar reset ----------------
__global__ void __launch_bounds__(1024) prep_kernel(
    const float* __restrict__ wk, const float* __restrict__ wv,
    const float* __restrict__ ln_w, const float* __restrict__ ln_b) {
    const int t = threadIdx.x;  // 1024
#pragma unroll
    for (int i = 0; i < 8; i++) {
        int idx = t + i * 1024;
        int n = idx >> 8, kel = idx & 255;
        float w = ((n < 16) ? wk[n * D_ + kel] : wv[(n - 16) * D_ + kel]) * ln_w[kel];
        __nv_bfloat16 h = __float2bfloat16(w);
        __nv_bfloat16 l = __float2bfloat16(w - __bfloat162float(h));
        g_wbh[idx] = *(unsigned short*)&h;
        g_wbl[idx] = *(unsigned short*)&l;
    }
    // c1/c2: one warp per output column (fp32, from raw weights)
    {
        int w = t >> 5, l = t & 31;
        const float* wr = (w < 16) ? &wk[w * D_] : &wv[(w - 16) * D_];
        float c1 = 0.f, c2 = 0.f;
#pragma unroll
        for (int j = 0; j < 8; j++) {
            int d = l + j * 32;
            float wv_ = wr[d];
            c1 = fmaf(wv_, ln_w[d], c1);
            c2 = fmaf(wv_, ln_b[d], c2);
        }
#pragma unroll
        for (int o = 16; o >= 1; o >>= 1) {
            c1 += __shfl_xor_sync(0xffffffffu, c1, o);
            c2 += __shfl_xor_sync(0xffffffffu, c2, o);
        }
        if (l == 0) {
            g_c1[w] = c1;
            g_c2[w] = c2;
        }
    }
#pragma unroll
    for (int i = 0; i < 12; i++) g_num3[t + i * 1024] = 0.f;
    if (t < 768) g_den3[t] = 0.f;
    if (t == 0) g_bar = 0u;
}

// ---------------- lnproj via mma.sync bf16 (2-term split, LN in fp32 epilogue) ----------------
// Block: 256 threads (8 warps), 128 rows, N=32, K=256.
// C[m=w-col 32][n=x-row] = w[m][k] * x[n][k]  (A=w row-major, B=x "col-major" == [n][k] rows)
// smem (bytes): xh [128][528] @0, xl @67584, wh [32][528] @135168, wl @152064,
//               mu[128] @168960, rs[128] @169472; total 169984
#define XP_BYTES 528
#define XH_OFF 0
#define XL_OFF 67584
#define WH_OFF 135168
#define WL_OFF 152064
#define MU_OFF 168960
#define RS_OFF 169472
#define LM_SMEM_BYTES 169984

__device__ __forceinline__ void ldsm_x4(uint32_t* f, uint32_t addr) {
    asm volatile("ldmatrix.sync.aligned.m8n8.x4.shared.b16 {%0,%1,%2,%3}, [%4];"
                 : "=r"(f[0]), "=r"(f[1]), "=r"(f[2]), "=r"(f[3]) : "r"(addr));
}
__device__ __forceinline__ void ldsm_x2(uint32_t* f, uint32_t addr) {
    asm volatile("ldmatrix.sync.aligned.m8n8.x2.shared.b16 {%0,%1}, [%2];"
                 : "=r"(f[0]), "=r"(f[1]) : "r"(addr));
}
__device__ __forceinline__ void mma_bf16(float* c, const uint32_t* a, const uint32_t* b) {
    asm volatile(
        "mma.sync.aligned.m16n8k16.row.col.f32.bf16.bf16.f32 "
        "{%0,%1,%2,%3}, {%4,%5,%6,%7}, {%8,%9}, {%0,%1,%2,%3};"
        : "+f"(c[0]), "+f"(c[1]), "+f"(c[2]), "+f"(c[3])
        : "r"(a[0]), "r"(a[1]), "r"(a[2]), "r"(a[3]), "r"(b[0]), "r"(b[1]));
}

__global__ void __launch_bounds__(256) lnproj_mma_kernel(const float* __restrict__ in) {
    extern __shared__ char smem[];
    const uint32_t sb = smem_to_u32(smem);
    const int t = threadIdx.x;
    const int wid = t >> 5;
    const int lane = t & 31;
    const long long row0 = (long long)blockIdx.x * 128;

    // stage w tiles (plain [n][k] -> pitch-528 rows), 4096 u32 each
    for (int i = t; i < 4096; i += 256) {
        int n = i >> 7;              // u32 i covers elements 2i,2i+1: n = 2i>>8
        int kk = (i & 127) * 2;
        uint32_t vh = ((const uint32_t*)g_wbh)[i];
        uint32_t vl = ((const uint32_t*)g_wbl)[i];
        *(uint32_t*)(smem + WH_OFF + n * XP_BYTES + kk * 2) = vh;
        *(uint32_t*)(smem + WL_OFF + n * XP_BYTES + kk * 2) = vl;
    }

    // stage x rows (hi+lo bf16) + fp32 LN stats (2 threads per row, proven pattern)
    {
        const int r = t >> 1, half = t & 1;
        const float4* src = (const float4*)(in + (row0 + r) * D_ + half * 128);
        uint32_t* dh = (uint32_t*)(smem + XH_OFF + r * XP_BYTES + half * 256);
        uint32_t* dl = (uint32_t*)(smem + XL_OFF + r * XP_BYTES + half * 256);
        float sum = 0.f, ssq = 0.f;
#pragma unroll 8
        for (int j = 0; j < 32; j++) {
            float4 v = src[j];
            sum += (v.x + v.y) + (v.z + v.w);
            ssq = fmaf(v.x, v.x, ssq);
            ssq = fmaf(v.y, v.y, ssq);
            ssq = fmaf(v.z, v.z, ssq);
            ssq = fmaf(v.w, v.w, ssq);
            __nv_bfloat162 h0 = __floats2bfloat162_rn(v.x, v.y);
            __nv_bfloat162 h1 = __floats2bfloat162_rn(v.z, v.w);
            float2 f0 = __bfloat1622float2(h0);
            float2 f1 = __bfloat1622float2(h1);
            __nv_bfloat162 l0 = __floats2bfloat162_rn(v.x - f0.x, v.y - f0.y);
            __nv_bfloat162 l1 = __floats2bfloat162_rn(v.z - f1.x, v.w - f1.y);
            dh[2 * j] = *(uint32_t*)&h0;
            dh[2 * j + 1] = *(uint32_t*)&h1;
            dl[2 * j] = *(uint32_t*)&l0;
            dl[2 * j + 1] = *(uint32_t*)&l1;
        }
        sum += __shfl_xor_sync(0xffffffffu, sum, 1);
        ssq += __shfl_xor_sync(0xffffffffu, ssq, 1);
        if (half == 0) {
            float mu = sum * (1.f / 256.f);
            float var = ssq * (1.f / 256.f) - mu * mu;
            ((float*)(smem + MU_OFF))[r] = mu;
            ((float*)(smem + RS_OFF))[r] = rsqrtf(var + LN_EPS);
        }
    }
    __syncthreads();

    // MMA mainloop: warp owns x-rows [wid*16, wid*16+16), all 32 w-cols
    float acc[2][2][4];
#pragma unroll
    for (int mt = 0; mt < 2; mt++)
#pragma unroll
        for (int nt = 0; nt < 2; nt++)
#pragma unroll
            for (int r = 0; r < 4; r++) acc[mt][nt][r] = 0.f;

    const int n0 = wid * 16;
    const int am = lane & 15;               // A row within 16-row tile
    const int ak = (lane >> 4) << 3;        // A k-offset (0 or 8)
    const int bi = lane & 15;               // B lane pattern (replicated for lanes 16-31)
    const int bn = bi & 7;                  // B row within 8-row tile
    const int bk = ((bi >> 3) & 1) << 3;    // B k-offset (0 or 8)

#pragma unroll 4
    for (int ks = 0; ks < 16; ks++) {
        const int k0 = ks * 16;
        uint32_t ah[2][4], al[2][4], bh[2][2], bl[2][2];
#pragma unroll
        for (int mt = 0; mt < 2; mt++) {
            uint32_t ro = (uint32_t)((mt * 16 + am) * XP_BYTES + (k0 + ak) * 2);
            ldsm_x4(ah[mt], sb + WH_OFF + ro);
            ldsm_x4(al[mt], sb + WL_OFF + ro);
        }
#pragma unroll
        for (int nt = 0; nt < 2; nt++) {
            uint32_t ro = (uint32_t)((n0 + nt * 8 + bn) * XP_BYTES + (k0 + bk) * 2);
            ldsm_x2(bh[nt], sb + XH_OFF + ro);
            ldsm_x2(bl[nt], sb + XL_OFF + ro);
        }
#pragma unroll
        for (int mt = 0; mt < 2; mt++)
#pragma unroll
            for (int nt = 0; nt < 2; nt++) {
                mma_bf16(acc[mt][nt], ah[mt], bh[nt]);
                mma_bf16(acc[mt][nt], ah[mt], bl[nt]);
                mma_bf16(acc[mt][nt], al[mt], bh[nt]);
            }
    }

    // epilogue: C[m=col][n=x-row]; apply LN correction in fp32, write g_kv
    const float* mup = (const float*)(smem + MU_OFF);
    const float* rsp = (const float*)(smem + RS_OFF);
#pragma unroll
    for (int mt = 0; mt < 2; mt++)
#pragma unroll
        for (int nt = 0; nt < 2; nt++)
#pragma unroll
            for (int r = 0; r < 4; r++) {
                int col = mt * 16 + (lane >> 2) + ((r >> 1) << 3);
                int xrow = n0 + nt * 8 + ((lane & 3) << 1) + (r & 1);
                float v = acc[mt][nt][r];
                float o = fmaf(rsp[xrow], v - mup[xrow] * g_c1[col], g_c2[col]);
                g_kv[(row0 + xrow) * 32 + col] = o;
            }
}

// ---------------- persistent mainloop (R10-pass verbatim) ----------------
#define ML_SMEM_FLOATS 13728

__device__ __forceinline__ void grid_barrier(unsigned target) {
    __syncthreads();
    if (threadIdx.x == 0) {
        __threadfence();
        atomicAdd(&g_bar, 1u);
        while (*((volatile unsigned*)&g_bar) < target) {
            __nanosleep(64);
        }
        __threadfence();
    }
    __syncthreads();
}

__global__ void __launch_bounds__(ML_THREADS, 4) mainloop_kernel(
    const float* __restrict__ init_slots,
    const float* __restrict__ ln_s_w, const float* __restrict__ ln_s_b,
    const float* __restrict__ wq,
    const float* __restrict__ w_ih, const float* __restrict__ w_hh,
    const float* __restrict__ b_ih, const float* __restrict__ b_hh,
    const float* __restrict__ ln_m_w, const float* __restrict__ ln_m_b,
    const float* __restrict__ w1, const float* __restrict__ b1,
    const float* __restrict__ w2, const float* __restrict__ b2,
    float* __restrict__ out_slots, float* __restrict__ out_attn) {
    extern __shared__ float smf[];
    float* kvs = smf;
    float* slb = smf + 9216;
    float* qlo = smf + 9344;
    float* S1 = smf + 9472;
    float* S2 = smf + 11648;

    const int bx = blockIdx.x;
    const int b = bx >> 4;
    const int grp = bx & 15;
    const int n0 = grp * ML_NT;
    const int t = threadIdx.x;          // 0..255
    const int k = t & 7;
    const int g = t >> 3;               // 0..31
    const int lane = t & 31;
    const int warp = t >> 5;            // 0..7

    {
        const float4* src = (const float4*)(g_kv + ((long long)b * N_ + n0) * 32);
#pragma unroll
        for (int i = 0; i < 8; i++) {
            int idx = t + i * ML_THREADS;
            int r = idx >> 3, f = idx & 7;
            *(float4*)&kvs[r * KV_PITCH + 4 * f] = src[idx];
        }
    }
    if (t < 128) slb[t] = init_slots[b * 128 + t];
    __syncthreads();

    if (t < K_) {
        float x[S_];
        float s = 0.f;
#pragma unroll
        for (int j = 0; j < S_; j++) {
            x[j] = slb[t * S_ + j];
            s += x[j];
        }
        float mu = s * (1.f / 16.f);
        float ss = 0.f;
#pragma unroll
        for (int j = 0; j < S_; j++) {
            float d = x[j] - mu;
            ss = fmaf(d, d, ss);
        }
        float rs = rsqrtf(ss * (1.f / 16.f) + LN_EPS);
        float y[S_];
#pragma unroll
        for (int j = 0; j < S_; j++) y[j] = (x[j] - mu) * rs * __ldg(ln_s_w + j) + __ldg(ln_s_b + j);
#pragma unroll
        for (int tt = 0; tt < S_; tt++) {
            float q = 0.f;
#pragma unroll
            for (int j = 0; j < S_; j++) q = fmaf(y[j], __ldg(wq + tt * S_ + j), q);
            qlo[t * S_ + tt] = q;
        }
    }
    __syncthreads();

    for (int it = 0; it < 3; it++) {
        float qr[S_];
#pragma unroll
        for (int s = 0; s < S_; s++) qr[s] = qlo[k * S_ + s];
        float num[S_];
#pragma unroll
        for (int s = 0; s < S_; s++) num[s] = 0.f;
        float den = 0.f;

#pragma unroll 2
        for (int j = 0; j < ML_NT / 32; j++) {
            int nl = g + 32 * j;
            const float* kn = &kvs[nl * KV_PITCH];
            float logit = 0.f;
#pragma unroll
            for (int s = 0; s < S_; s++) logit = fmaf(qr[s], kn[s], logit);
            logit *= SCALE_;
            float m = logit;
            m = fmaxf(m, __shfl_xor_sync(0xffffffffu, m, 1));
            m = fmaxf(m, __shfl_xor_sync(0xffffffffu, m, 2));
            m = fmaxf(m, __shfl_xor_sync(0xffffffffu, m, 4));
            float e = __expf(logit - m);
            float sum = e;
            sum += __shfl_xor_sync(0xffffffffu, sum, 1);
            sum += __shfl_xor_sync(0xffffffffu, sum, 2);
            sum += __shfl_xor_sync(0xffffffffu, sum, 4);
            float a = e / sum + EPS_;
            if (it == 2) S2[k * (ML_NT + 4) + nl] = a;
            den += a;
            const float* vn = kn + 16;
#pragma unroll
            for (int s = 0; s < S_; s++) num[s] = fmaf(a, vn[s], num[s]);
        }

#pragma unroll
        for (int o = 8; o <= 16; o <<= 1) {
#pragma unroll
            for (int s = 0; s < S_; s++) num[s] += __shfl_xor_sync(0xffffffffu, num[s], o);
            den += __shfl_xor_sync(0xffffffffu, den, o);
        }
        __syncthreads();
        if (lane < 8) {
            float* rp = &S1[(warp * 8 + lane) * 17];
#pragma unroll
            for (int s = 0; s < S_; s++) rp[s] = num[s];
            rp[16] = den;
        }
        __syncthreads();
        if (t < 136) {
            int k2 = t / 17, s2 = t % 17;
            float v = 0.f;
#pragma unroll
            for (int w = 0; w < 8; w++) v += S1[(w * 8 + k2) * 17 + s2];
            if (s2 < 16)
                atomicAdd(&g_num3[it * 4096 + b * 128 + k2 * 16 + s2], v);
            else
                atomicAdd(&g_den3[it * 256 + b * K_ + k2], v);
        }

        grid_barrier((unsigned)ML_GRID * (unsigned)(it + 1));

        if (t < 128) {
            float u_num = __ldcg(&g_num3[it * 4096 + b * 128 + t]);
            float u_den = __ldcg(&g_den3[it * 256 + b * K_ + (t >> 4)]);
            S1[t] = u_num / u_den;
        }

        if (it == 2) {
            if (t < K_) qlo[t] = 1.0f / __ldcg(&g_den3[it * 256 + b * K_ + t]);
            __syncthreads();
#pragma unroll 4
            for (int i = t; i < K_ * ML_NT; i += ML_THREADS) {
                int kk = i >> 8, nn = i & (ML_NT - 1);
                out_attn[((long long)(b * K_ + kk)) * N_ + n0 + nn] =
                    S2[kk * (ML_NT + 4) + nn] * qlo[kk];
            }
        }
        __syncthreads();

        for (int i = t; i < 768; i += ML_THREADS) {
            S2[i] = __ldg(w_ih + i);
            S2[768 + i] = __ldg(w_hh + i);
        }
        __syncthreads();
        for (int idx = t; idx < 384; idx += ML_THREADS) {
            int kk = idx / 48, j = idx % 48;
            float gi = __ldg(b_ih + j), gh = __ldg(b_hh + j);
#pragma unroll
            for (int s = 0; s < S_; s++) {
                gi = fmaf(S1[kk * S_ + s], S2[j * S_ + s], gi);
                gh = fmaf(slb[kk * S_ + s], S2[768 + j * S_ + s], gh);
            }
            S1[384 + idx] = gi;
            S1[768 + idx] = gh;
        }
        __syncthreads();
        if (t < 128) {
            int kk = t >> 4, s = t & 15;
            float ir = S1[384 + kk * 48 + s], hr = S1[768 + kk * 48 + s];
            float iz = S1[384 + kk * 48 + 16 + s], hz = S1[768 + kk * 48 + 16 + s];
            float inn = S1[384 + kk * 48 + 32 + s], hn = S1[768 + kk * 48 + 32 + s];
            float r = 1.f / (1.f + __expf(-(ir + hr)));
            float z = 1.f / (1.f + __expf(-(iz + hz)));
            float n = tanhf(inn + r * hn);
            float h = (1.f - z) * n + z * slb[t];
            S1[128 + t] = h;
            float s1 = h, s2 = h * h;
#pragma unroll
            for (int o = 1; o <= 8; o <<= 1) {
                s1 += __shfl_xor_sync(0xffffffffu, s1, o);
                s2 += __shfl_xor_sync(0xffffffffu, s2, o);
            }
            float mu = s1 * (1.f / 16.f);
            float var = s2 * (1.f / 16.f) - mu * mu;
            float rs = rsqrtf(var + LN_EPS);
            S1[256 + t] = (h - mu) * rs * __ldg(ln_m_w + s) + __ldg(ln_m_b + s);
        }
        __syncthreads();
        for (int i = t; i < H_ * S_; i += ML_THREADS) S2[i] = __ldg(w1 + i);
        __syncthreads();
        for (int idx = t; idx < K_ * H_; idx += ML_THREADS) {
            int kk = idx >> 7, hh = idx & 127;
            float acc = __ldg(b1 + hh);
#pragma unroll
            for (int s = 0; s < S_; s++) acc = fmaf(S1[256 + kk * S_ + s], S2[hh * S_ + s], acc);
            S1[1152 + idx] = fmaxf(acc, 0.f);
        }
        __syncthreads();
        for (int i = t; i < S_ * H_; i += ML_THREADS) S2[i] = __ldg(w2 + i);
        __syncthreads();
        float res = 0.f;
        if (t < 128) {
            int kk = t >> 4, s = t & 15;
            float acc = __ldg(b2 + s);
#pragma unroll 8
            for (int h = 0; h < H_; h++) acc = fmaf(S1[1152 + kk * H_ + h], S2[s * H_ + h], acc);
            res = S1[128 + t] + acc;
        }

        if (it == 2) {
            if (grp == 0 && t < 128) out_slots[b * 128 + t] = res;
        } else {
            __syncthreads();
            if (t < 128) slb[t] = res;
            __syncthreads();
            if (t < K_) {
                float x[S_];
                float s = 0.f;
#pragma unroll
                for (int j = 0; j < S_; j++) {
                    x[j] = slb[t * S_ + j];
                    s += x[j];
                }
                float mu = s * (1.f / 16.f);
                float ss = 0.f;
#pragma unroll
                for (int j = 0; j < S_; j++) {
                    float d = x[j] - mu;
                    ss = fmaf(d, d, ss);
                }
                float rs = rsqrtf(ss * (1.f / 16.f) + LN_EPS);
                float y[S_];
#pragma unroll
                for (int j = 0; j < S_; j++)
                    y[j] = (x[j] - mu) * rs * __ldg(ln_s_w + j) + __ldg(ln_s_b + j);
#pragma unroll
                for (int tt = 0; tt < S_; tt++) {
                    float q = 0.f;
#pragma unroll
                    for (int j = 0; j < S_; j++) q = fmaf(y[j], __ldg(wq + tt * S_ + j), q);
                    qlo[t * S_ + tt] = q;
                }
            }
            __syncthreads();
        }
    }
}

// ---------------- launch: 3 graph nodes ----------------
extern "C" void kernel_launch(void* const* d_in, const int* in_sizes, int n_in,
                              void* d_out, int out_size) {
    const float* inputs = (const float*)d_in[0];
    const float* init_slots = (const float*)d_in[1];
    const float* ln_in_w = (const float*)d_in[2];
    const float* ln_in_b = (const float*)d_in[3];
    const float* ln_s_w = (const float*)d_in[4];
    const float* ln_s_b = (const float*)d_in[5];
    const float* ln_m_w = (const float*)d_in[6];
    const float* ln_m_b = (const float*)d_in[7];
    const float* wq = (const float*)d_in[8];
    const float* wk = (const float*)d_in[9];
    const float* wv = (const float*)d_in[10];
    const float* w_ih = (const float*)d_in[11];
    const float* w_hh = (const float*)d_in[12];
    const float* b_ih = (const float*)d_in[13];
    const float* b_hh = (const float*)d_in[14];
    const float* mlp_w1 = (const float*)d_in[15];
    const float* mlp_b1 = (const float*)d_in[16];
    const float* mlp_w2 = (const float*)d_in[17];
    const float* mlp_b2 = (const float*)d_in[18];

    float* out_slots = (float*)d_out;
    float* out_attn = out_slots + B_ * K_ * S_;

    cudaFuncSetAttribute(lnproj_mma_kernel, cudaFuncAttributeMaxDynamicSharedMemorySize, LM_SMEM_BYTES);
    const int ml_smem = ML_SMEM_FLOATS * sizeof(float);
    cudaFuncSetAttribute(mainloop_kernel, cudaFuncAttributeMaxDynamicSharedMemorySize, ml_smem);

    prep_kernel<<<1, 1024>>>(wk, wv, ln_in_w, ln_in_b);
    lnproj_mma_kernel<<<(B_ * N_) / 128, 256, LM_SMEM_BYTES>>>(inputs);
    mainloop_kernel<<<ML_GRID, ML_THREADS, ml_smem>>>(
        init_slots, ln_s_w, ln_s_b, wq, w_ih, w_hh, b_ih, b_hh,
        ln_m_w, ln_m_b, mlp_w1, mlp_b1, mlp_w2, mlp_b2, out_slots, out_attn);
}

// round 13
// speedup vs baseline: 1.2216x; 1.0019x over previous
#include <cuda_runtime.h>
#include <cuda_bf16.h>
#include <math.h>
#include <stdint.h>

// Problem constants
#define B_   32
#define N_   4096
#define D_   256
#define S_   16
#define K_   8
#define H_   128
#define LN_EPS 1e-5f
#define EPS_ 1e-8f
#define SCALE_ 0.25f

#define ML_GRID 512          // 32 batches x 16 groups of 256 n
#define ML_NT 256            // n per block
#define ML_THREADS 256
#define KV_PITCH 36

// ---------------- device scratch ----------------
__device__ float g_c1[32];
__device__ float g_c2[32];
__device__ __align__(16) float g_kv[(long long)B_ * N_ * 32];  // [b][n][k0..15|v0..15]
__device__ __align__(16) unsigned short g_wbh[32 * 256];       // bf16 hi w  [n][k] row-major
__device__ __align__(16) unsigned short g_wbl[32 * 256];       // bf16 lo w
__device__ float g_num3[3 * B_ * K_ * S_];      // per-iteration accumulators
__device__ float g_den3[3 * B_ * K_];
__device__ unsigned g_bar;

__device__ __forceinline__ uint32_t smem_to_u32(const void* smem_ptr) {
    uint32_t addr;
    asm("{ .reg .u64 tmp; cvta.to.shared.u64 tmp, %1; cvt.u32.u64 %0, tmp; }"
        : "=r"(addr) : "l"(smem_ptr));
    return addr;
}

// ---------------- prep (R12-pass verbatim) ----------------
__global__ void __launch_bounds__(1024) prep_kernel(
    const float* __restrict__ wk, const float* __restrict__ wv,
    const float* __restrict__ ln_w, const float* __restrict__ ln_b) {
    const int t = threadIdx.x;  // 1024
#pragma unroll
    for (int i = 0; i < 8; i++) {
        int idx = t + i * 1024;
        int n = idx >> 8, kel = idx & 255;
        float w = ((n < 16) ? wk[n * D_ + kel] : wv[(n - 16) * D_ + kel]) * ln_w[kel];
        __nv_bfloat16 h = __float2bfloat16(w);
        __nv_bfloat16 l = __float2bfloat16(w - __bfloat162float(h));
        g_wbh[idx] = *(unsigned short*)&h;
        g_wbl[idx] = *(unsigned short*)&l;
    }
    {
        int w = t >> 5, l = t & 31;
        const float* wr = (w < 16) ? &wk[w * D_] : &wv[(w - 16) * D_];
        float c1 = 0.f, c2 = 0.f;
#pragma unroll
        for (int j = 0; j < 8; j++) {
            int d = l + j * 32;
            float wv_ = wr[d];
            c1 = fmaf(wv_, ln_w[d], c1);
            c2 = fmaf(wv_, ln_b[d], c2);
        }
#pragma unroll
        for (int o = 16; o >= 1; o >>= 1) {
            c1 += __shfl_xor_sync(0xffffffffu, c1, o);
            c2 += __shfl_xor_sync(0xffffffffu, c2, o);
        }
        if (l == 0) {
            g_c1[w] = c1;
            g_c2[w] = c2;
        }
    }
#pragma unroll
    for (int i = 0; i < 12; i++) g_num3[t + i * 1024] = 0.f;
    if (t < 768) g_den3[t] = 0.f;
    if (t == 0) g_bar = 0u;
}

// ---------------- lnproj via mma.sync bf16 (512 threads, 16 warps) ----------------
// Block: 512 threads, 128 x-rows, N=32 w-cols, K=256.
// C[m=w-col][n=x-row] = w[m][k] * x[n][k]; warp owns 8 x-rows, all 32 cols.
#define XP_BYTES 528
#define XH_OFF 0
#define XL_OFF 67584
#define WH_OFF 135168
#define WL_OFF 152064
#define MU_OFF 168960
#define RS_OFF 169472
#define LM_SMEM_BYTES 169984

__device__ __forceinline__ void ldsm_x4(uint32_t* f, uint32_t addr) {
    asm volatile("ldmatrix.sync.aligned.m8n8.x4.shared.b16 {%0,%1,%2,%3}, [%4];"
                 : "=r"(f[0]), "=r"(f[1]), "=r"(f[2]), "=r"(f[3]) : "r"(addr));
}
__device__ __forceinline__ void ldsm_x2(uint32_t* f, uint32_t addr) {
    asm volatile("ldmatrix.sync.aligned.m8n8.x2.shared.b16 {%0,%1}, [%2];"
                 : "=r"(f[0]), "=r"(f[1]) : "r"(addr));
}
__device__ __forceinline__ void mma_bf16(float* c, const uint32_t* a, const uint32_t* b) {
    asm volatile(
        "mma.sync.aligned.m16n8k16.row.col.f32.bf16.bf16.f32 "
        "{%0,%1,%2,%3}, {%4,%5,%6,%7}, {%8,%9}, {%0,%1,%2,%3};"
        : "+f"(c[0]), "+f"(c[1]), "+f"(c[2]), "+f"(c[3])
        : "r"(a[0]), "r"(a[1]), "r"(a[2]), "r"(a[3]), "r"(b[0]), "r"(b[1]));
}

__global__ void __launch_bounds__(512) lnproj_mma_kernel(const float* __restrict__ in) {
    extern __shared__ char smem[];
    const uint32_t sb = smem_to_u32(smem);
    const int t = threadIdx.x;
    const int wid = t >> 5;            // 0..15
    const int lane = t & 31;
    const long long row0 = (long long)blockIdx.x * 128;

    // stage w tiles (plain [n][k] -> pitch-528 rows), 4096 u32 each
    for (int i = t; i < 4096; i += 512) {
        int n = i >> 7;
        int kk = (i & 127) * 2;
        uint32_t vh = ((const uint32_t*)g_wbh)[i];
        uint32_t vl = ((const uint32_t*)g_wbl)[i];
        *(uint32_t*)(smem + WH_OFF + n * XP_BYTES + kk * 2) = vh;
        *(uint32_t*)(smem + WL_OFF + n * XP_BYTES + kk * 2) = vl;
    }

    // stage x rows (hi+lo bf16) + fp32 LN stats (R12-proven pattern; warps 0-7 only)
    if (t < 256) {
        const int r = t >> 1, half = t & 1;
        const float4* src = (const float4*)(in + (row0 + r) * D_ + half * 128);
        uint32_t* dh = (uint32_t*)(smem + XH_OFF + r * XP_BYTES + half * 256);
        uint32_t* dl = (uint32_t*)(smem + XL_OFF + r * XP_BYTES + half * 256);
        float sum = 0.f, ssq = 0.f;
#pragma unroll 8
        for (int j = 0; j < 32; j++) {
            float4 v = src[j];
            sum += (v.x + v.y) + (v.z + v.w);
            ssq = fmaf(v.x, v.x, ssq);
            ssq = fmaf(v.y, v.y, ssq);
            ssq = fmaf(v.z, v.z, ssq);
            ssq = fmaf(v.w, v.w, ssq);
            __nv_bfloat162 h0 = __floats2bfloat162_rn(v.x, v.y);
            __nv_bfloat162 h1 = __floats2bfloat162_rn(v.z, v.w);
            float2 f0 = __bfloat1622float2(h0);
            float2 f1 = __bfloat1622float2(h1);
            __nv_bfloat162 l0 = __floats2bfloat162_rn(v.x - f0.x, v.y - f0.y);
            __nv_bfloat162 l1 = __floats2bfloat162_rn(v.z - f1.x, v.w - f1.y);
            dh[2 * j] = *(uint32_t*)&h0;
            dh[2 * j + 1] = *(uint32_t*)&h1;
            dl[2 * j] = *(uint32_t*)&l0;
            dl[2 * j + 1] = *(uint32_t*)&l1;
        }
        sum += __shfl_xor_sync(0xffffffffu, sum, 1);
        ssq += __shfl_xor_sync(0xffffffffu, ssq, 1);
        if (half == 0) {
            float mu = sum * (1.f / 256.f);
            float var = ssq * (1.f / 256.f) - mu * mu;
            ((float*)(smem + MU_OFF))[r] = mu;
            ((float*)(smem + RS_OFF))[r] = rsqrtf(var + LN_EPS);
        }
    }
    __syncthreads();

    // MMA mainloop: warp owns x-rows [wid*8, wid*8+8), all 32 w-cols
    float acc[2][4];
#pragma unroll
    for (int mt = 0; mt < 2; mt++)
#pragma unroll
        for (int r = 0; r < 4; r++) acc[mt][r] = 0.f;

    const int n0 = wid * 8;
    const int am = lane & 15;               // A row within 16-row tile
    const int ak = (lane >> 4) << 3;        // A k-offset (0 or 8)
    const int bi = lane & 15;               // B lane pattern
    const int bn = bi & 7;                  // B row within 8-row tile
    const int bk = ((bi >> 3) & 1) << 3;    // B k-offset (0 or 8)

#pragma unroll 4
    for (int ks = 0; ks < 16; ks++) {
        const int k0 = ks * 16;
        uint32_t ah[2][4], al[2][4], bh[2], bl[2];
#pragma unroll
        for (int mt = 0; mt < 2; mt++) {
            uint32_t ro = (uint32_t)((mt * 16 + am) * XP_BYTES + (k0 + ak) * 2);
            ldsm_x4(ah[mt], sb + WH_OFF + ro);
            ldsm_x4(al[mt], sb + WL_OFF + ro);
        }
        {
            uint32_t ro = (uint32_t)((n0 + bn) * XP_BYTES + (k0 + bk) * 2);
            ldsm_x2(bh, sb + XH_OFF + ro);
            ldsm_x2(bl, sb + XL_OFF + ro);
        }
#pragma unroll
        for (int mt = 0; mt < 2; mt++) {
            mma_bf16(acc[mt], ah[mt], bh);
            mma_bf16(acc[mt], ah[mt], bl);
            mma_bf16(acc[mt], al[mt], bh);
        }
    }

    // epilogue: C[m=col][n=x-row]; apply LN correction in fp32, write g_kv
    const float* mup = (const float*)(smem + MU_OFF);
    const float* rsp = (const float*)(smem + RS_OFF);
#pragma unroll
    for (int mt = 0; mt < 2; mt++)
#pragma unroll
        for (int r = 0; r < 4; r++) {
            int col = mt * 16 + (lane >> 2) + ((r >> 1) << 3);
            int xrow = n0 + ((lane & 3) << 1) + (r & 1);
            float v = acc[mt][r];
            float o = fmaf(rsp[xrow], v - mup[xrow] * g_c1[col], g_c2[col]);
            g_kv[(row0 + xrow) * 32 + col] = o;
        }
}

// ---------------- persistent mainloop (R12-pass verbatim) ----------------
#define ML_SMEM_FLOATS 13728

__device__ __forceinline__ void grid_barrier(unsigned target) {
    __syncthreads();
    if (threadIdx.x == 0) {
        __threadfence();
        atomicAdd(&g_bar, 1u);
        while (*((volatile unsigned*)&g_bar) < target) {
            __nanosleep(64);
        }
        __threadfence();
    }
    __syncthreads();
}

__global__ void __launch_bounds__(ML_THREADS, 4) mainloop_kernel(
    const float* __restrict__ init_slots,
    const float* __restrict__ ln_s_w, const float* __restrict__ ln_s_b,
    const float* __restrict__ wq,
    const float* __restrict__ w_ih, const float* __restrict__ w_hh,
    const float* __restrict__ b_ih, const float* __restrict__ b_hh,
    const float* __restrict__ ln_m_w, const float* __restrict__ ln_m_b,
    const float* __restrict__ w1, const float* __restrict__ b1,
    const float* __restrict__ w2, const float* __restrict__ b2,
    float* __restrict__ out_slots, float* __restrict__ out_attn) {
    extern __shared__ float smf[];
    float* kvs = smf;
    float* slb = smf + 9216;
    float* qlo = smf + 9344;
    float* S1 = smf + 9472;
    float* S2 = smf + 11648;

    const int bx = blockIdx.x;
    const int b = bx >> 4;
    const int grp = bx & 15;
    const int n0 = grp * ML_NT;
    const int t = threadIdx.x;          // 0..255
    const int k = t & 7;
    const int g = t >> 3;               // 0..31
    const int lane = t & 31;
    const int warp = t >> 5;            // 0..7

    {
        const float4* src = (const float4*)(g_kv + ((long long)b * N_ + n0) * 32);
#pragma unroll
        for (int i = 0; i < 8; i++) {
            int idx = t + i * ML_THREADS;
            int r = idx >> 3, f = idx & 7;
            *(float4*)&kvs[r * KV_PITCH + 4 * f] = src[idx];
        }
    }
    if (t < 128) slb[t] = init_slots[b * 128 + t];
    __syncthreads();

    if (t < K_) {
        float x[S_];
        float s = 0.f;
#pragma unroll
        for (int j = 0; j < S_; j++) {
            x[j] = slb[t * S_ + j];
            s += x[j];
        }
        float mu = s * (1.f / 16.f);
        float ss = 0.f;
#pragma unroll
        for (int j = 0; j < S_; j++) {
            float d = x[j] - mu;
            ss = fmaf(d, d, ss);
        }
        float rs = rsqrtf(ss * (1.f / 16.f) + LN_EPS);
        float y[S_];
#pragma unroll
        for (int j = 0; j < S_; j++) y[j] = (x[j] - mu) * rs * __ldg(ln_s_w + j) + __ldg(ln_s_b + j);
#pragma unroll
        for (int tt = 0; tt < S_; tt++) {
            float q = 0.f;
#pragma unroll
            for (int j = 0; j < S_; j++) q = fmaf(y[j], __ldg(wq + tt * S_ + j), q);
            qlo[t * S_ + tt] = q;
        }
    }
    __syncthreads();

    for (int it = 0; it < 3; it++) {
        float qr[S_];
#pragma unroll
        for (int s = 0; s < S_; s++) qr[s] = qlo[k * S_ + s];
        float num[S_];
#pragma unroll
        for (int s = 0; s < S_; s++) num[s] = 0.f;
        float den = 0.f;

#pragma unroll 2
        for (int j = 0; j < ML_NT / 32; j++) {
            int nl = g + 32 * j;
            const float* kn = &kvs[nl * KV_PITCH];
            float logit = 0.f;
#pragma unroll
            for (int s = 0; s < S_; s++) logit = fmaf(qr[s], kn[s], logit);
            logit *= SCALE_;
            float m = logit;
            m = fmaxf(m, __shfl_xor_sync(0xffffffffu, m, 1));
            m = fmaxf(m, __shfl_xor_sync(0xffffffffu, m, 2));
            m = fmaxf(m, __shfl_xor_sync(0xffffffffu, m, 4));
            float e = __expf(logit - m);
            float sum = e;
            sum += __shfl_xor_sync(0xffffffffu, sum, 1);
            sum += __shfl_xor_sync(0xffffffffu, sum, 2);
            sum += __shfl_xor_sync(0xffffffffu, sum, 4);
            float a = e / sum + EPS_;
            if (it == 2) S2[k * (ML_NT + 4) + nl] = a;
            den += a;
            const float* vn = kn + 16;
#pragma unroll
            for (int s = 0; s < S_; s++) num[s] = fmaf(a, vn[s], num[s]);
        }

#pragma unroll
        for (int o = 8; o <= 16; o <<= 1) {
#pragma unroll
            for (int s = 0; s < S_; s++) num[s] += __shfl_xor_sync(0xffffffffu, num[s], o);
            den += __shfl_xor_sync(0xffffffffu, den, o);
        }
        __syncthreads();
        if (lane < 8) {
            float* rp = &S1[(warp * 8 + lane) * 17];
#pragma unroll
            for (int s = 0; s < S_; s++) rp[s] = num[s];
            rp[16] = den;
        }
        __syncthreads();
        if (t < 136) {
            int k2 = t / 17, s2 = t % 17;
            float v = 0.f;
#pragma unroll
            for (int w = 0; w < 8; w++) v += S1[(w * 8 + k2) * 17 + s2];
            if (s2 < 16)
                atomicAdd(&g_num3[it * 4096 + b * 128 + k2 * 16 + s2], v);
            else
                atomicAdd(&g_den3[it * 256 + b * K_ + k2], v);
        }

        grid_barrier((unsigned)ML_GRID * (unsigned)(it + 1));

        if (t < 128) {
            float u_num = __ldcg(&g_num3[it * 4096 + b * 128 + t]);
            float u_den = __ldcg(&g_den3[it * 256 + b * K_ + (t >> 4)]);
            S1[t] = u_num / u_den;
        }

        if (it == 2) {
            if (t < K_) qlo[t] = 1.0f / __ldcg(&g_den3[it * 256 + b * K_ + t]);
            __syncthreads();
#pragma unroll 4
            for (int i = t; i < K_ * ML_NT; i += ML_THREADS) {
                int kk = i >> 8, nn = i & (ML_NT - 1);
                out_attn[((long long)(b * K_ + kk)) * N_ + n0 + nn] =
                    S2[kk * (ML_NT + 4) + nn] * qlo[kk];
            }
        }
        __syncthreads();

        for (int i = t; i < 768; i += ML_THREADS) {
            S2[i] = __ldg(w_ih + i);
            S2[768 + i] = __ldg(w_hh + i);
        }
        __syncthreads();
        for (int idx = t; idx < 384; idx += ML_THREADS) {
            int kk = idx / 48, j = idx % 48;
            float gi = __ldg(b_ih + j), gh = __ldg(b_hh + j);
#pragma unroll
            for (int s = 0; s < S_; s++) {
                gi = fmaf(S1[kk * S_ + s], S2[j * S_ + s], gi);
                gh = fmaf(slb[kk * S_ + s], S2[768 + j * S_ + s], gh);
            }
            S1[384 + idx] = gi;
            S1[768 + idx] = gh;
        }
        __syncthreads();
        if (t < 128) {
            int kk = t >> 4, s = t & 15;
            float ir = S1[384 + kk * 48 + s], hr = S1[768 + kk * 48 + s];
            float iz = S1[384 + kk * 48 + 16 + s], hz = S1[768 + kk * 48 + 16 + s];
            float inn = S1[384 + kk * 48 + 32 + s], hn = S1[768 + kk * 48 + 32 + s];
            float r = 1.f / (1.f + __expf(-(ir + hr)));
            float z = 1.f / (1.f + __expf(-(iz + hz)));
            float n = tanhf(inn + r * hn);
            float h = (1.f - z) * n + z * slb[t];
            S1[128 + t] = h;
            float s1 = h, s2 = h * h;
#pragma unroll
            for (int o = 1; o <= 8; o <<= 1) {
                s1 += __shfl_xor_sync(0xffffffffu, s1, o);
                s2 += __shfl_xor_sync(0xffffffffu, s2, o);
            }
            float mu = s1 * (1.f / 16.f);
            float var = s2 * (1.f / 16.f) - mu * mu;
            float rs = rsqrtf(var + LN_EPS);
            S1[256 + t] = (h - mu) * rs * __ldg(ln_m_w + s) + __ldg(ln_m_b + s);
        }
        __syncthreads();
        for (int i = t; i < H_ * S_; i += ML_THREADS) S2[i] = __ldg(w1 + i);
        __syncthreads();
        for (int idx = t; idx < K_ * H_; idx += ML_THREADS) {
            int kk = idx >> 7, hh = idx & 127;
            float acc = __ldg(b1 + hh);
#pragma unroll
            for (int s = 0; s < S_; s++) acc = fmaf(S1[256 + kk * S_ + s], S2[hh * S_ + s], acc);
            S1[1152 + idx] = fmaxf(acc, 0.f);
        }
        __syncthreads();
        for (int i = t; i < S_ * H_; i += ML_THREADS) S2[i] = __ldg(w2 + i);
        __syncthreads();
        float res = 0.f;
        if (t < 128) {
            int kk = t >> 4, s = t & 15;
            float acc = __ldg(b2 + s);
#pragma unroll 8
            for (int h = 0; h < H_; h++) acc = fmaf(S1[1152 + kk * H_ + h], S2[s * H_ + h], acc);
            res = S1[128 + t] + acc;
        }

        if (it == 2) {
            if (grp == 0 && t < 128) out_slots[b * 128 + t] = res;
        } else {
            __syncthreads();
            if (t < 128) slb[t] = res;
            __syncthreads();
            if (t < K_) {
                float x[S_];
                float s = 0.f;
#pragma unroll
                for (int j = 0; j < S_; j++) {
                    x[j] = slb[t * S_ + j];
                    s += x[j];
                }
                float mu = s * (1.f / 16.f);
                float ss = 0.f;
#pragma unroll
                for (int j = 0; j < S_; j++) {
                    float d = x[j] - mu;
                    ss = fmaf(d, d, ss);
                }
                float rs = rsqrtf(ss * (1.f / 16.f) + LN_EPS);
                float y[S_];
#pragma unroll
                for (int j = 0; j < S_; j++)
                    y[j] = (x[j] - mu) * rs * __ldg(ln_s_w + j) + __ldg(ln_s_b + j);
#pragma unroll
                for (int tt = 0; tt < S_; tt++) {
                    float q = 0.f;
#pragma unroll
                    for (int j = 0; j < S_; j++) q = fmaf(y[j], __ldg(wq + tt * S_ + j), q);
                    qlo[t * S_ + tt] = q;
                }
            }
            __syncthreads();
        }
    }
}

// ---------------- launch: 3 graph nodes ----------------
extern "C" void kernel_launch(void* const* d_in, const int* in_sizes, int n_in,
                              void* d_out, int out_size) {
    const float* inputs = (const float*)d_in[0];
    const float* init_slots = (const float*)d_in[1];
    const float* ln_in_w = (const float*)d_in[2];
    const float* ln_in_b = (const float*)d_in[3];
    const float* ln_s_w = (const float*)d_in[4];
    const float* ln_s_b = (const float*)d_in[5];
    const float* ln_m_w = (const float*)d_in[6];
    const float* ln_m_b = (const float*)d_in[7];
    const float* wq = (const float*)d_in[8];
    const float* wk = (const float*)d_in[9];
    const float* wv = (const float*)d_in[10];
    const float* w_ih = (const float*)d_in[11];
    const float* w_hh = (const float*)d_in[12];
    const float* b_ih = (const float*)d_in[13];
    const float* b_hh = (const float*)d_in[14];
    const float* mlp_w1 = (const float*)d_in[15];
    const float* mlp_b1 = (const float*)d_in[16];
    const float* mlp_w2 = (const float*)d_in[17];
    const float* mlp_b2 = (const float*)d_in[18];

    float* out_slots = (float*)d_out;
    float* out_attn = out_slots + B_ * K_ * S_;

    cudaFuncSetAttribute(lnproj_mma_kernel, cudaFuncAttributeMaxDynamicSharedMemorySize, LM_SMEM_BYTES);
    const int ml_smem = ML_SMEM_FLOATS * sizeof(float);
    cudaFuncSetAttribute(mainloop_kernel, cudaFuncAttributeMaxDynamicSharedMemorySize, ml_smem);

    prep_kernel<<<1, 1024>>>(wk, wv, ln_in_w, ln_in_b);
    lnproj_mma_kernel<<<(B_ * N_) / 128, 512, LM_SMEM_BYTES>>>(inputs);
    mainloop_kernel<<<ML_GRID, ML_THREADS, ml_smem>>>(
        init_slots, ln_s_w, ln_s_b, wq, w_ih, w_hh, b_ih, b_hh,
        ln_m_w, ln_m_b, mlp_w1, mlp_b1, mlp_w2, mlp_b2, out_slots, out_attn);
}